// round 6
// baseline (speedup 1.0000x reference)
#include <cuda_runtime.h>
#include <math.h>
#include <stdint.h>

#define D 128
#define C 10
#define NMAX 4096
#define BT 128
#define BK 32
#define STRIDE 36                    // f32 words per tile row (bank-spread pad)

#define TILE_B (128 * STRIDE * 4)    // 18432 bytes
#define OFF_AHI   0
#define OFF_ALO   (OFF_AHI + TILE_B)
#define OFF_BHI   (OFF_ALO + TILE_B)
#define OFF_BLO   (OFF_BHI + TILE_B)
#define OFF_PROJA (OFF_BLO + TILE_B)          // float[10][132]
#define OFF_PROJB (OFF_PROJA + 5280)
#define OFF_ASQ   (OFF_PROJB + 5280)
#define OFF_AP    (OFF_ASQ + 512)
#define OFF_AIW   (OFF_AP + 512)
#define OFF_AIC   (OFF_AIW + 512)
#define OFF_BSQ   (OFF_AIC + 512)
#define OFF_BP    (OFF_BSQ + 512)
#define OFF_BIW   (OFF_BP + 512)
#define OFF_BIC   (OFF_BIW + 512)
#define OFF_ACL   (OFF_BIC + 512)
#define OFF_BCL   (OFF_ACL + 512)
#define OFF_RA0   (OFF_BCL + 512)
#define OFF_RA1   (OFF_RA0 + 512)
#define OFF_RA2   (OFF_RA1 + 512)
#define OFF_TB0   (OFF_RA2 + 512)
#define OFF_TB1   (OFF_TB0 + 512)
#define OFF_TB2   (OFF_TB1 + 512)
#define OFF_ICT   (OFF_TB2 + 512)             // float[16]
#define OFF_SACC  (OFF_ICT + 64)              // double[32]
#define SMEM_DYN  (OFF_SACC + 256)            // 92800 bytes

// -------- device scratch (zero-init; finalize self-resets) --------
__device__ double g_Sacc[32];
__device__ int    g_counts[C];
__device__ float  g_sq[NMAX];
__device__ float  g_proj[NMAX * C];
__device__ int    g_cls[NMAX];
__device__ float  g_pcl[NMAX];
__device__ float  g_invwnCls[NMAX];
__device__ unsigned int g_done = 0;

__device__ __forceinline__ int clampC(int v) { return v < 0 ? 0 : (v >= C ? C - 1 : v); }

__device__ __forceinline__ float tf32r(float x) {
    uint32_t u; asm("cvt.rna.tf32.f32 %0, %1;" : "=r"(u) : "f"(x));
    return __uint_as_float(u);
}
// rsqrt without MUFU: magic seed + 2 Newton steps (rel err ~4e-6)
__device__ __forceinline__ float fast_rsqrt(float x) {
    float y = __int_as_float(0x5f3759dfu - (__float_as_int(x) >> 1));
    float xh = -0.5f * x;
    y = y * fmaf(xh, y * y, 1.5f);
    y = y * fmaf(xh, y * y, 1.5f);
    return y;
}
__device__ __forceinline__ void mma_tf32(float* d, const uint32_t* a, const uint32_t* b) {
    asm volatile(
        "mma.sync.aligned.m16n8k8.row.col.f32.tf32.tf32.f32 "
        "{%0,%1,%2,%3}, {%4,%5,%6,%7}, {%8,%9}, {%0,%1,%2,%3};"
        : "+f"(d[0]), "+f"(d[1]), "+f"(d[2]), "+f"(d[3])
        : "r"(a[0]), "r"(a[1]), "r"(a[2]), "r"(a[3]), "r"(b[0]), "r"(b[1]));
}

// ---------------- prep: counts + per-row sq, proj[10], derived scalars -------
__global__ void prep(const float* __restrict__ pred,
                     const int* __restrict__ target,
                     const float* __restrict__ W, int N)
{
    __shared__ float Wsh[C][D];
    __shared__ float wnInv[C];
    __shared__ int   cnt[C];
    int tid = threadIdx.x;
    if (tid < C) cnt[tid] = 0;
    for (int i = tid; i < C * D; i += blockDim.x) Wsh[i / D][i % D] = W[i];
    __syncthreads();
    if (tid < C) {
        float s = 0.f;
        #pragma unroll 16
        for (int k = 0; k < D; k++) { float w = Wsh[tid][k]; s = fmaf(w, w, s); }
        wnInv[tid] = 1.0f / fmaxf(sqrtf(s), 1e-8f);
    }
    __syncthreads();

    int r = blockIdx.x * blockDim.x + tid;
    if (r < N) {
        int cl = clampC(target[r]);
        atomicAdd(&cnt[cl], 1);

        const float4* p4 = (const float4*)(pred + (size_t)r * D);
        float sq = 0.f;
        float proj[C];
        #pragma unroll
        for (int c = 0; c < C; c++) proj[c] = 0.f;
        #pragma unroll 4
        for (int q = 0; q < D / 4; q++) {
            float4 v = p4[q];
            float vv[4] = {v.x, v.y, v.z, v.w};
            #pragma unroll
            for (int j = 0; j < 4; j++) {
                float p = vv[j];
                int k = q * 4 + j;
                sq = fmaf(p, p, sq);
                #pragma unroll
                for (int c = 0; c < C; c++) proj[c] = fmaf(p, Wsh[c][k], proj[c]);
            }
        }
        g_sq[r]  = sq;
        g_cls[r] = cl;
        #pragma unroll
        for (int c = 0; c < C; c++) g_proj[(size_t)r * C + c] = proj[c];
        g_pcl[r]      = proj[cl];
        g_invwnCls[r] = wnInv[cl];
    }
    __syncthreads();
    if (tid < C && cnt[tid] > 0) atomicAdd(&g_counts[tid], cnt[tid]);
}

// ---------------- main: HMMA-tf32x3 Gram tiles + fused loss epilogue ---------
__global__ __launch_bounds__(256, 2)
void pairKernel(const float* __restrict__ pred, float* __restrict__ out, int nb)
{
    extern __shared__ char smc[];
    float*  AHf   = (float*)(smc + OFF_AHI);
    float*  ALf   = (float*)(smc + OFF_ALO);
    float*  BHf   = (float*)(smc + OFF_BHI);
    float*  BLf   = (float*)(smc + OFF_BLO);
    const uint32_t* AHu = (const uint32_t*)AHf;
    const uint32_t* ALu = (const uint32_t*)ALf;
    const uint32_t* BHu = (const uint32_t*)BHf;
    const uint32_t* BLu = (const uint32_t*)BLf;
    float*  projA = (float*)(smc + OFF_PROJA);
    float*  projB = (float*)(smc + OFF_PROJB);
    float*  aSq = (float*)(smc + OFF_ASQ);
    float*  aP  = (float*)(smc + OFF_AP);
    float*  aIW = (float*)(smc + OFF_AIW);
    float*  aIC = (float*)(smc + OFF_AIC);
    float*  bSq = (float*)(smc + OFF_BSQ);
    float*  bP  = (float*)(smc + OFF_BP);
    float*  bIW = (float*)(smc + OFF_BIW);
    float*  bIC = (float*)(smc + OFF_BIC);
    int*    aCl = (int*)(smc + OFF_ACL);
    int*    bCl = (int*)(smc + OFF_BCL);
    float*  rA0 = (float*)(smc + OFF_RA0);
    float*  rA1 = (float*)(smc + OFF_RA1);
    float*  rA2 = (float*)(smc + OFF_RA2);
    float*  tB0 = (float*)(smc + OFF_TB0);
    float*  tB1 = (float*)(smc + OFF_TB1);
    float*  tB2 = (float*)(smc + OFF_TB2);
    float*  icT = (float*)(smc + OFF_ICT);
    double* sacc = (double*)(smc + OFF_SACC);

    int tid  = threadIdx.x;
    int lane = tid & 31, wid = tid >> 5;
    int wm = wid >> 2, wn = wid & 3;       // warp grid 2(m) x 4(n)
    int g2 = lane >> 2, tig = lane & 3;

    int idx = blockIdx.x;
    int bi = (int)(((float)(2 * nb + 1)
             - sqrtf((float)((2 * nb + 1) * (2 * nb + 1) - 8 * idx))) * 0.5f);
    while ((bi + 1) * nb - ((bi + 1) * bi) / 2 <= idx) bi++;
    while (bi * nb - (bi * (bi - 1)) / 2 > idx) bi--;
    int bj = bi + (idx - (bi * nb - (bi * (bi - 1)) / 2));
    int aBase = bi * BT, bBase = bj * BT;
    bool offd = (bi != bj);

    // ---- meta fill ----
    if (tid < 32) sacc[tid] = 0.0;
    if (tid < C)  icT[tid] = 1.0f / (float)max(g_counts[tid], 1);
    if (tid < BT) {
        int ga = aBase + tid, gb = bBase + tid;
        aSq[tid] = g_sq[ga]; aP[tid] = g_pcl[ga]; aIW[tid] = g_invwnCls[ga];
        aCl[tid] = g_cls[ga];
        bSq[tid] = g_sq[gb]; bP[tid] = g_pcl[gb]; bIW[tid] = g_invwnCls[gb];
        bCl[tid] = g_cls[gb];
        rA0[tid] = 0.f; rA1[tid] = 0.f; rA2[tid] = 0.f;
        tB0[tid] = 0.f; tB1[tid] = 0.f; tB2[tid] = 0.f;
    }
    for (int i = tid; i < C * BT; i += 256) {
        int c = i >> 7, b = i & 127;
        projB[c * 132 + b] = g_proj[(size_t)(bBase + b) * C + c];
        projA[c * 132 + b] = g_proj[(size_t)(aBase + b) * C + c];
    }
    __syncthreads();
    if (tid < BT) {
        aIC[tid] = icT[aCl[tid]];
        bIC[tid] = icT[bCl[tid]];
    }

    float dacc[4][4][4];
    #pragma unroll
    for (int a = 0; a < 4; a++)
        #pragma unroll
        for (int b = 0; b < 4; b++)
            #pragma unroll
            for (int e = 0; e < 4; e++) dacc[a][b][e] = 0.f;

    // gmem prefetch buffers: 4 slots each for A and B
    int ldRow[4], ldQ[4];
    #pragma unroll
    for (int i = 0; i < 4; i++) { int s = tid + i * 256; ldRow[i] = s >> 3; ldQ[i] = s & 7; }

    float4 bufA[4], bufB[4];
    #pragma unroll
    for (int i = 0; i < 4; i++) {
        bufA[i] = *(const float4*)&pred[(size_t)(aBase + ldRow[i]) * D + ldQ[i] * 4];
        bufB[i] = *(const float4*)&pred[(size_t)(bBase + ldRow[i]) * D + ldQ[i] * 4];
    }

    for (int ch = 0; ch < 4; ch++) {
        __syncthreads();
        #pragma unroll
        for (int i = 0; i < 4; i++) {
            int w0 = ldRow[i] * STRIDE + ldQ[i] * 4;
            float4 v = bufA[i];
            float4 h = make_float4(tf32r(v.x), tf32r(v.y), tf32r(v.z), tf32r(v.w));
            float4 l = make_float4(tf32r(v.x - h.x), tf32r(v.y - h.y),
                                   tf32r(v.z - h.z), tf32r(v.w - h.w));
            *(float4*)&AHf[w0] = h;
            *(float4*)&ALf[w0] = l;
            float4 u = bufB[i];
            float4 h2 = make_float4(tf32r(u.x), tf32r(u.y), tf32r(u.z), tf32r(u.w));
            float4 l2 = make_float4(tf32r(u.x - h2.x), tf32r(u.y - h2.y),
                                    tf32r(u.z - h2.z), tf32r(u.w - h2.w));
            *(float4*)&BHf[w0] = h2;
            *(float4*)&BLf[w0] = l2;
        }
        __syncthreads();
        if (ch < 3) {
            int kb = (ch + 1) * BK;
            #pragma unroll
            for (int i = 0; i < 4; i++) {
                bufA[i] = *(const float4*)&pred[(size_t)(aBase + ldRow[i]) * D + kb + ldQ[i] * 4];
                bufB[i] = *(const float4*)&pred[(size_t)(bBase + ldRow[i]) * D + kb + ldQ[i] * 4];
            }
        }
        // ---- mma phase: 4 k8-steps x 3 split-combos ----
        #pragma unroll
        for (int s = 0; s < 4; s++) {
            int kc = s * 8;
            uint32_t Bh[4][2], Bl[4][2], Af[4][4];
            #pragma unroll
            for (int fn = 0; fn < 4; fn++) {
                int cw = (wn * 32 + fn * 8 + g2) * STRIDE + kc + tig;
                Bh[fn][0] = BHu[cw]; Bh[fn][1] = BHu[cw + 4];
                Bl[fn][0] = BLu[cw]; Bl[fn][1] = BLu[cw + 4];
            }
            #pragma unroll
            for (int fm = 0; fm < 4; fm++) {
                int rw = (wm * 64 + fm * 16 + g2) * STRIDE + kc + tig;
                Af[fm][0] = AHu[rw];               Af[fm][1] = AHu[rw + 8 * STRIDE];
                Af[fm][2] = AHu[rw + 4];           Af[fm][3] = AHu[rw + 8 * STRIDE + 4];
            }
            #pragma unroll
            for (int fm = 0; fm < 4; fm++)
                #pragma unroll
                for (int fn = 0; fn < 4; fn++) mma_tf32(dacc[fm][fn], Af[fm], Bh[fn]);
            #pragma unroll
            for (int fm = 0; fm < 4; fm++)
                #pragma unroll
                for (int fn = 0; fn < 4; fn++) mma_tf32(dacc[fm][fn], Af[fm], Bl[fn]);
            #pragma unroll
            for (int fm = 0; fm < 4; fm++) {
                int rw = (wm * 64 + fm * 16 + g2) * STRIDE + kc + tig;
                Af[fm][0] = ALu[rw];               Af[fm][1] = ALu[rw + 8 * STRIDE];
                Af[fm][2] = ALu[rw + 4];           Af[fm][3] = ALu[rw + 8 * STRIDE + 4];
            }
            #pragma unroll
            for (int fm = 0; fm < 4; fm++)
                #pragma unroll
                for (int fn = 0; fn < 4; fn++) mma_tf32(dacc[fm][fn], Af[fm], Bh[fn]);
        }
    }

    // -------- epilogue: per-pair loss from mma fragments --------
    float t0[8], t1[8], t2[8];
    #pragma unroll
    for (int j = 0; j < 8; j++) { t0[j] = 0.f; t1[j] = 0.f; t2[j] = 0.f; }

    #pragma unroll
    for (int fm = 0; fm < 4; fm++) {
        #pragma unroll
        for (int rr = 0; rr < 2; rr++) {
            int r = wm * 64 + fm * 16 + g2 + rr * 8;
            int   ca  = aCl[r];
            float pa  = aP[r], iw = aIW[r], ica = aIC[r], sqa = aSq[r];
            const float* pjr = projB + ca * 132;
            float s0 = 0.f, s1 = 0.f, s2 = 0.f;
            #pragma unroll
            for (int fn = 0; fn < 4; fn++) {
                #pragma unroll
                for (int hh = 0; hh < 2; hh++) {
                    int c = wn * 32 + fn * 8 + 2 * tig + hh;
                    float gv = dacc[fm][fn][rr * 2 + hh];
                    float d2 = fmaxf(sqa + bSq[c] - 2.0f * gv, 0.0f) + 1e-16f;
                    float invdn = fast_rsqrt(d2);
                    int cb = bCl[c];
                    if (cb != ca) {
                        float w = ica * bIC[c];
                        float MA = (pa - pjr[c]) * iw * invdn;
                        s0 += w; s1 = fmaf(w, MA, s1); s2 = fmaf(w * MA, MA, s2);
                        if (offd) {
                            float MB = (bP[c] - projA[cb * 132 + r]) * bIW[c] * invdn;
                            int j = fn * 2 + hh;
                            t0[j] += w; t1[j] = fmaf(w, MB, t1[j]); t2[j] = fmaf(w * MB, MB, t2[j]);
                        }
                    }
                }
            }
            atomicAdd(&rA0[r], s0); atomicAdd(&rA1[r], s1); atomicAdd(&rA2[r], s2);
        }
    }
    if (offd) {
        #pragma unroll
        for (int j = 0; j < 8; j++) {
            int c = wn * 32 + (j >> 1) * 8 + 2 * tig + (j & 1);
            atomicAdd(&tB0[c], t0[j]); atomicAdd(&tB1[c], t1[j]); atomicAdd(&tB2[c], t2[j]);
        }
    }
    __syncthreads();

    if (tid < BT) {
        int ca = aCl[tid];
        atomicAdd(&sacc[ca * 3 + 0], (double)rA0[tid]);
        atomicAdd(&sacc[ca * 3 + 1], (double)rA1[tid]);
        atomicAdd(&sacc[ca * 3 + 2], (double)rA2[tid]);
    } else if (offd) {
        int c = tid - BT;
        int cb = bCl[c];
        atomicAdd(&sacc[cb * 3 + 0], (double)tB0[c]);
        atomicAdd(&sacc[cb * 3 + 1], (double)tB1[c]);
        atomicAdd(&sacc[cb * 3 + 2], (double)tB2[c]);
    }
    __syncthreads();
    if (tid < 30) atomicAdd(&g_Sacc[tid], sacc[tid]);

    // -------- fused finalize --------
    __threadfence();
    __syncthreads();
    if (tid == 0) {
        unsigned int old = atomicAdd(&g_done, 1u);
        if (old == gridDim.x - 1) {
            __threadfence();
            int e = 0;
            for (int c = 0; c < C; c++) e += (g_counts[c] > 0);
            double ed  = (double)e;
            double inv = 1.0 / (ed - 1.0);
            double l1 = 0.0, l2 = 0.0;
            for (int c = 0; c < C; c++) {
                if (g_counts[c] > 0) {
                    double S0 = g_Sacc[c * 3 + 0];
                    double S1 = g_Sacc[c * 3 + 1];
                    double S2 = g_Sacc[c * 3 + 2];
                    l1 += (S0 - 2.0 * S1 + S2) * inv;
                    double mm = S1 * inv;
                    double mv = (S2 - 2.0 * mm * S1 + mm * mm * S0) * inv;
                    l2 += fabs(mv / mm);
                }
            }
            out[0] = (float)(l1 / ed);
            out[1] = (float)(l2 / ed);
            for (int i = 0; i < 32; i++) g_Sacc[i] = 0.0;
            for (int c = 0; c < C; c++)  g_counts[c] = 0;
            g_done = 0;
        }
    }
}

// ---------------- launch ----------------
extern "C" void kernel_launch(void* const* d_in, const int* in_sizes, int n_in,
                              void* d_out, int out_size)
{
    const float* pred   = (const float*)d_in[0];
    const int*   target = (const int*)d_in[1];   // JAX x64-disabled: int64 -> int32
    const float* W      = (const float*)d_in[2];
    int N = in_sizes[0] / D;                     // 4096
    int nb = N / BT;                             // 32
    int nblk = nb * (nb + 1) / 2;                // 528

    static int attrSet = 0;
    if (!attrSet) {
        cudaFuncSetAttribute(pairKernel, cudaFuncAttributeMaxDynamicSharedMemorySize, SMEM_DYN);
        attrSet = 1;
    }

    prep<<<(N + 127) / 128, 128>>>(pred, target, W, N);
    pairKernel<<<nblk, 256, SMEM_DYN>>>(pred, (float*)d_out, nb);
}

// round 7
// speedup vs baseline: 1.6063x; 1.6063x over previous
#include <cuda_runtime.h>
#include <math.h>
#include <stdint.h>

#define D 128
#define C 10
#define NMAX 4096
#define BT 128

// -------- device scratch (zero-init; finalize self-resets) --------
__device__ double g_Sacc[32];
__device__ int    g_counts[C];
__device__ float  g_sq[NMAX];
__device__ float  g_proj[NMAX * C];
__device__ int    g_cls[NMAX];
__device__ float  g_pcl[NMAX];
__device__ float  g_invwnCls[NMAX];
__device__ unsigned int g_done = 0;

__device__ __forceinline__ int clampC(int v) { return v < 0 ? 0 : (v >= C ? C - 1 : v); }

// rsqrt without MUFU: magic seed + 2 Newton steps (rel err ~4e-6)
__device__ __forceinline__ float fast_rsqrt(float x) {
    float y = __int_as_float(0x5f3759dfu - (__float_as_int(x) >> 1));
    float xh = -0.5f * x;
    y = y * fmaf(xh, y * y, 1.5f);
    y = y * fmaf(xh, y * y, 1.5f);
    return y;
}
__device__ __forceinline__ void mma_tf32(float* d, const uint32_t* a, const uint32_t* b) {
    asm volatile(
        "mma.sync.aligned.m16n8k8.row.col.f32.tf32.tf32.f32 "
        "{%0,%1,%2,%3}, {%4,%5,%6,%7}, {%8,%9}, {%0,%1,%2,%3};"
        : "+f"(d[0]), "+f"(d[1]), "+f"(d[2]), "+f"(d[3])
        : "r"(a[0]), "r"(a[1]), "r"(a[2]), "r"(a[3]), "r"(b[0]), "r"(b[1]));
}
// hi = truncate-to-tf32 via mask; lo = exact residual (HMMA truncates lo's tail)
__device__ __forceinline__ void split_tf(float v, uint32_t& h, uint32_t& l) {
    h = __float_as_uint(v) & 0xffffe000u;
    l = __float_as_uint(v - __uint_as_float(h));
}

// ---------------- prep: counts + per-row sq, proj[10], derived scalars -------
__global__ void prep(const float* __restrict__ pred,
                     const int* __restrict__ target,
                     const float* __restrict__ W, int N)
{
    __shared__ float Wsh[C][D];
    __shared__ float wnInv[C];
    __shared__ int   cnt[C];
    int tid = threadIdx.x;
    if (tid < C) cnt[tid] = 0;
    for (int i = tid; i < C * D; i += blockDim.x) Wsh[i / D][i % D] = W[i];
    __syncthreads();
    if (tid < C) {
        float s = 0.f;
        #pragma unroll 16
        for (int k = 0; k < D; k++) { float w = Wsh[tid][k]; s = fmaf(w, w, s); }
        wnInv[tid] = 1.0f / fmaxf(sqrtf(s), 1e-8f);
    }
    __syncthreads();

    int r = blockIdx.x * blockDim.x + tid;
    if (r < N) {
        int cl = clampC(target[r]);
        atomicAdd(&cnt[cl], 1);

        const float4* p4 = (const float4*)(pred + (size_t)r * D);
        float sq = 0.f;
        float proj[C];
        #pragma unroll
        for (int c = 0; c < C; c++) proj[c] = 0.f;
        #pragma unroll 4
        for (int q = 0; q < D / 4; q++) {
            float4 v = p4[q];
            float vv[4] = {v.x, v.y, v.z, v.w};
            #pragma unroll
            for (int j = 0; j < 4; j++) {
                float p = vv[j];
                int k = q * 4 + j;
                sq = fmaf(p, p, sq);
                #pragma unroll
                for (int c = 0; c < C; c++) proj[c] = fmaf(p, Wsh[c][k], proj[c]);
            }
        }
        g_sq[r]  = sq;
        g_cls[r] = cl;
        #pragma unroll
        for (int c = 0; c < C; c++) g_proj[(size_t)r * C + c] = proj[c];
        g_pcl[r]      = proj[cl];
        g_invwnCls[r] = wnInv[cl];
    }
    __syncthreads();
    if (tid < C && cnt[tid] > 0) atomicAdd(&g_counts[tid], cnt[tid]);
}

// ------- main: gmem-direct fragment HMMA tf32x3 + fused loss epilogue --------
__global__ __launch_bounds__(256, 2)
void pairKernel(const float* __restrict__ pred, float* __restrict__ out, int nb)
{
    __shared__ float projA[C][132];
    __shared__ float projB[C][132];
    __shared__ float aSq[BT], aP[BT], aIW[BT], aIC[BT];
    __shared__ float bSq[BT], bP[BT], bIW[BT], bIC[BT];
    __shared__ int   aCl[BT], bCl[BT];
    __shared__ float rA0[BT], rA1[BT], rA2[BT];
    __shared__ float tB0[BT], tB1[BT], tB2[BT];
    __shared__ float icT[16];
    __shared__ double sacc[32];

    int tid  = threadIdx.x;
    int lane = tid & 31, wid = tid >> 5;
    int wm = wid >> 2, wn = wid & 3;      // warp grid 2(m) x 4(n)
    int g2 = lane >> 2, tig = lane & 3;

    int idx = blockIdx.x;
    int bi = (int)(((float)(2 * nb + 1)
             - sqrtf((float)((2 * nb + 1) * (2 * nb + 1) - 8 * idx))) * 0.5f);
    while ((bi + 1) * nb - ((bi + 1) * bi) / 2 <= idx) bi++;
    while (bi * nb - (bi * (bi - 1)) / 2 > idx) bi--;
    int bj = bi + (idx - (bi * nb - (bi * (bi - 1)) / 2));
    int aBase = bi * BT, bBase = bj * BT;
    bool offd = (bi != bj);

    // ---- meta fill ----
    if (tid < 32) sacc[tid] = 0.0;
    if (tid < C)  icT[tid] = 1.0f / (float)max(g_counts[tid], 1);
    if (tid < BT) {
        int ga = aBase + tid, gb = bBase + tid;
        aSq[tid] = g_sq[ga]; aP[tid] = g_pcl[ga]; aIW[tid] = g_invwnCls[ga];
        aCl[tid] = g_cls[ga];
        bSq[tid] = g_sq[gb]; bP[tid] = g_pcl[gb]; bIW[tid] = g_invwnCls[gb];
        bCl[tid] = g_cls[gb];
        rA0[tid] = 0.f; rA1[tid] = 0.f; rA2[tid] = 0.f;
        tB0[tid] = 0.f; tB1[tid] = 0.f; tB2[tid] = 0.f;
    }
    for (int i = tid; i < C * BT; i += 256) {
        int c = i >> 7, b = i & 127;
        projB[c][b] = g_proj[(size_t)(bBase + b) * C + c];
        projA[c][b] = g_proj[(size_t)(aBase + b) * C + c];
    }
    __syncthreads();
    if (tid < BT) {
        aIC[tid] = icT[aCl[tid]];
        bIC[tid] = icT[bCl[tid]];
    }

    float dacc[4][4][4];
    #pragma unroll
    for (int a = 0; a < 4; a++)
        #pragma unroll
        for (int b = 0; b < 4; b++)
            #pragma unroll
            for (int e = 0; e < 4; e++) dacc[a][b][e] = 0.f;

    // gmem-direct fragment pointers.
    // k-permutation: frag slot k^=t <-> phys 2t ; k^=t+4 <-> phys 2t+1
    // (identical for A and B, so the dot product is unchanged)
    const float* pA0 = pred + (size_t)(aBase + wm * 64 + g2) * D + 2 * tig;
    const float* pB0 = pred + (size_t)(bBase + wn * 32 + g2) * D + 2 * tig;

    #pragma unroll
    for (int ks = 0; ks < 16; ks++) {
        int kb = ks * 8;
        // load raw fp32 fragment pairs (LDG.64 each)
        float2 va[4][2], vb[4];
        #pragma unroll
        for (int fm = 0; fm < 4; fm++) {
            va[fm][0] = *(const float2*)(pA0 + fm * 16 * D + kb);
            va[fm][1] = *(const float2*)(pA0 + fm * 16 * D + 8 * D + kb);
        }
        #pragma unroll
        for (int fn = 0; fn < 4; fn++)
            vb[fn] = *(const float2*)(pB0 + fn * 8 * D + kb);

        // split hi/lo
        uint32_t Ah[4][4], Al[4][4], Bh[4][2], Bl[4][2];
        #pragma unroll
        for (int fm = 0; fm < 4; fm++) {
            split_tf(va[fm][0].x, Ah[fm][0], Al[fm][0]);   // a0: row g2,   k^=t
            split_tf(va[fm][1].x, Ah[fm][1], Al[fm][1]);   // a1: row g2+8, k^=t
            split_tf(va[fm][0].y, Ah[fm][2], Al[fm][2]);   // a2: row g2,   k^=t+4
            split_tf(va[fm][1].y, Ah[fm][3], Al[fm][3]);   // a3: row g2+8, k^=t+4
        }
        #pragma unroll
        for (int fn = 0; fn < 4; fn++) {
            split_tf(vb[fn].x, Bh[fn][0], Bl[fn][0]);      // b0: k^=t
            split_tf(vb[fn].y, Bh[fn][1], Bl[fn][1]);      // b1: k^=t+4
        }
        // 3xTF32: hi*hi + hi*lo + lo*hi
        #pragma unroll
        for (int fm = 0; fm < 4; fm++)
            #pragma unroll
            for (int fn = 0; fn < 4; fn++) mma_tf32(dacc[fm][fn], Ah[fm], Bh[fn]);
        #pragma unroll
        for (int fm = 0; fm < 4; fm++)
            #pragma unroll
            for (int fn = 0; fn < 4; fn++) mma_tf32(dacc[fm][fn], Ah[fm], Bl[fn]);
        #pragma unroll
        for (int fm = 0; fm < 4; fm++)
            #pragma unroll
            for (int fn = 0; fn < 4; fn++) mma_tf32(dacc[fm][fn], Al[fm], Bh[fn]);
    }

    // -------- epilogue: per-pair loss from mma fragments --------
    float t0[8], t1[8], t2[8];
    #pragma unroll
    for (int j = 0; j < 8; j++) { t0[j] = 0.f; t1[j] = 0.f; t2[j] = 0.f; }

    #pragma unroll
    for (int fm = 0; fm < 4; fm++) {
        #pragma unroll
        for (int rr = 0; rr < 2; rr++) {
            int r = wm * 64 + fm * 16 + g2 + rr * 8;
            int   ca  = aCl[r];
            float pa  = aP[r], iw = aIW[r], ica = aIC[r], sqa = aSq[r];
            float s0 = 0.f, s1 = 0.f, s2 = 0.f;
            #pragma unroll
            for (int fn = 0; fn < 4; fn++) {
                #pragma unroll
                for (int hh = 0; hh < 2; hh++) {
                    int c = wn * 32 + fn * 8 + 2 * tig + hh;
                    float gv = dacc[fm][fn][rr * 2 + hh];
                    float d2 = fmaxf(sqa + bSq[c] - 2.0f * gv, 0.0f) + 1e-16f;
                    float invdn = fast_rsqrt(d2);
                    int cb = bCl[c];
                    if (cb != ca) {
                        float w = ica * bIC[c];
                        float MA = (pa - projB[ca][c]) * iw * invdn;
                        s0 += w; s1 = fmaf(w, MA, s1); s2 = fmaf(w * MA, MA, s2);
                        if (offd) {
                            float MB = (bP[c] - projA[cb][r]) * bIW[c] * invdn;
                            int j = fn * 2 + hh;
                            t0[j] += w; t1[j] = fmaf(w, MB, t1[j]); t2[j] = fmaf(w * MB, MB, t2[j]);
                        }
                    }
                }
            }
            atomicAdd(&rA0[r], s0); atomicAdd(&rA1[r], s1); atomicAdd(&rA2[r], s2);
        }
    }
    if (offd) {
        #pragma unroll
        for (int j = 0; j < 8; j++) {
            int c = wn * 32 + (j >> 1) * 8 + 2 * tig + (j & 1);
            atomicAdd(&tB0[c], t0[j]); atomicAdd(&tB1[c], t1[j]); atomicAdd(&tB2[c], t2[j]);
        }
    }
    __syncthreads();

    if (tid < BT) {
        int ca = aCl[tid];
        atomicAdd(&sacc[ca * 3 + 0], (double)rA0[tid]);
        atomicAdd(&sacc[ca * 3 + 1], (double)rA1[tid]);
        atomicAdd(&sacc[ca * 3 + 2], (double)rA2[tid]);
    } else if (offd) {
        int c = tid - BT;
        int cb = bCl[c];
        atomicAdd(&sacc[cb * 3 + 0], (double)tB0[c]);
        atomicAdd(&sacc[cb * 3 + 1], (double)tB1[c]);
        atomicAdd(&sacc[cb * 3 + 2], (double)tB2[c]);
    }
    __syncthreads();
    if (tid < 30) atomicAdd(&g_Sacc[tid], sacc[tid]);

    // -------- fused finalize --------
    __threadfence();
    __syncthreads();
    if (tid == 0) {
        unsigned int old = atomicAdd(&g_done, 1u);
        if (old == gridDim.x - 1) {
            __threadfence();
            int e = 0;
            for (int c = 0; c < C; c++) e += (g_counts[c] > 0);
            double ed  = (double)e;
            double inv = 1.0 / (ed - 1.0);
            double l1 = 0.0, l2 = 0.0;
            for (int c = 0; c < C; c++) {
                if (g_counts[c] > 0) {
                    double S0 = g_Sacc[c * 3 + 0];
                    double S1 = g_Sacc[c * 3 + 1];
                    double S2 = g_Sacc[c * 3 + 2];
                    l1 += (S0 - 2.0 * S1 + S2) * inv;
                    double mm = S1 * inv;
                    double mv = (S2 - 2.0 * mm * S1 + mm * mm * S0) * inv;
                    l2 += fabs(mv / mm);
                }
            }
            out[0] = (float)(l1 / ed);
            out[1] = (float)(l2 / ed);
            for (int i = 0; i < 32; i++) g_Sacc[i] = 0.0;
            for (int c = 0; c < C; c++)  g_counts[c] = 0;
            g_done = 0;
        }
    }
}

// ---------------- launch ----------------
extern "C" void kernel_launch(void* const* d_in, const int* in_sizes, int n_in,
                              void* d_out, int out_size)
{
    const float* pred   = (const float*)d_in[0];
    const int*   target = (const int*)d_in[1];   // JAX x64-disabled: int64 -> int32
    const float* W      = (const float*)d_in[2];
    int N = in_sizes[0] / D;                     // 4096
    int nb = N / BT;                             // 32
    int nblk = nb * (nb + 1) / 2;                // 528

    prep<<<(N + 127) / 128, 128>>>(pred, target, W, N);
    pairKernel<<<nblk, 256>>>(pred, (float*)d_out, nb);
}

// round 8
// speedup vs baseline: 1.6799x; 1.0458x over previous
#include <cuda_runtime.h>
#include <math.h>
#include <stdint.h>

#define D 128
#define C 10
#define NMAX 4096
#define BT 128

// -------- device scratch (zero-init; finalize self-resets) --------
__device__ double g_Sacc[32];
__device__ int    g_counts[C];
__device__ float  g_sq[NMAX];
__device__ float  g_proj[NMAX * C];
__device__ int    g_cls[NMAX];
__device__ float  g_pcl[NMAX];
__device__ float  g_invwnCls[NMAX];
__device__ unsigned int g_done = 0;

__device__ __forceinline__ int clampC(int v) { return v < 0 ? 0 : (v >= C ? C - 1 : v); }

// rsqrt without MUFU: magic seed + 2 Newton steps (rel err ~4e-6)
__device__ __forceinline__ float fast_rsqrt(float x) {
    float y = __int_as_float(0x5f3759dfu - (__float_as_int(x) >> 1));
    float xh = -0.5f * x;
    y = y * fmaf(xh, y * y, 1.5f);
    y = y * fmaf(xh, y * y, 1.5f);
    return y;
}
__device__ __forceinline__ void mma_tf32(float* d, const uint32_t* a, const uint32_t* b) {
    asm volatile(
        "mma.sync.aligned.m16n8k8.row.col.f32.tf32.tf32.f32 "
        "{%0,%1,%2,%3}, {%4,%5,%6,%7}, {%8,%9}, {%0,%1,%2,%3};"
        : "+f"(d[0]), "+f"(d[1]), "+f"(d[2]), "+f"(d[3])
        : "r"(a[0]), "r"(a[1]), "r"(a[2]), "r"(a[3]), "r"(b[0]), "r"(b[1]));
}
__device__ __forceinline__ uint32_t cvt_tf32(float v) {
    uint32_t u; asm("cvt.rna.tf32.f32 %0, %1;" : "=r"(u) : "f"(v)); return u;
}

// ---------------- prep: counts + per-row sq, proj[10], derived scalars -------
__global__ void prep(const float* __restrict__ pred,
                     const int* __restrict__ target,
                     const float* __restrict__ W, int N)
{
    __shared__ float Wsh[C][D];
    __shared__ float wnInv[C];
    __shared__ int   cnt[C];
    int tid = threadIdx.x;
    if (tid < C) cnt[tid] = 0;
    for (int i = tid; i < C * D; i += blockDim.x) Wsh[i / D][i % D] = W[i];
    __syncthreads();
    if (tid < C) {
        float s = 0.f;
        #pragma unroll 16
        for (int k = 0; k < D; k++) { float w = Wsh[tid][k]; s = fmaf(w, w, s); }
        wnInv[tid] = 1.0f / fmaxf(sqrtf(s), 1e-8f);
    }
    __syncthreads();

    int r = blockIdx.x * blockDim.x + tid;
    if (r < N) {
        int cl = clampC(target[r]);
        atomicAdd(&cnt[cl], 1);

        const float4* p4 = (const float4*)(pred + (size_t)r * D);
        float sq = 0.f;
        float proj[C];
        #pragma unroll
        for (int c = 0; c < C; c++) proj[c] = 0.f;
        #pragma unroll 4
        for (int q = 0; q < D / 4; q++) {
            float4 v = p4[q];
            float vv[4] = {v.x, v.y, v.z, v.w};
            #pragma unroll
            for (int j = 0; j < 4; j++) {
                float p = vv[j];
                int k = q * 4 + j;
                sq = fmaf(p, p, sq);
                #pragma unroll
                for (int c = 0; c < C; c++) proj[c] = fmaf(p, Wsh[c][k], proj[c]);
            }
        }
        g_sq[r]  = sq;
        g_cls[r] = cl;
        #pragma unroll
        for (int c = 0; c < C; c++) g_proj[(size_t)r * C + c] = proj[c];
        g_pcl[r]      = proj[cl];
        g_invwnCls[r] = wnInv[cl];
    }
    __syncthreads();
    if (tid < C && cnt[tid] > 0) atomicAdd(&g_counts[tid], cnt[tid]);
}

// ------- main: gmem-direct fragment HMMA (single-pass tf32) + loss epilogue --
__global__ __launch_bounds__(256, 2)
void pairKernel(const float* __restrict__ pred, float* __restrict__ out, int nb)
{
    __shared__ float projA[C][132];
    __shared__ float projB[C][132];
    __shared__ float aSq[BT], aP[BT], aIW[BT], aIC[BT];
    __shared__ float bSq[BT], bP[BT], bIW[BT], bIC[BT];
    __shared__ int   aCl[BT], bCl[BT];
    __shared__ float rA0[BT], rA1[BT], rA2[BT];
    __shared__ float tB0[BT], tB1[BT], tB2[BT];
    __shared__ float icT[16];
    __shared__ double sacc[32];

    int tid  = threadIdx.x;
    int lane = tid & 31, wid = tid >> 5;
    int wm = wid >> 2, wn = wid & 3;      // warp grid 2(m) x 4(n)
    int g2 = lane >> 2, tig = lane & 3;

    int idx = blockIdx.x;
    int bi = (int)(((float)(2 * nb + 1)
             - sqrtf((float)((2 * nb + 1) * (2 * nb + 1) - 8 * idx))) * 0.5f);
    while ((bi + 1) * nb - ((bi + 1) * bi) / 2 <= idx) bi++;
    while (bi * nb - (bi * (bi - 1)) / 2 > idx) bi--;
    int bj = bi + (idx - (bi * nb - (bi * (bi - 1)) / 2));
    int aBase = bi * BT, bBase = bj * BT;
    bool offd = (bi != bj);

    // ---- meta fill ----
    if (tid < 32) sacc[tid] = 0.0;
    if (tid < C)  icT[tid] = 1.0f / (float)max(g_counts[tid], 1);
    if (tid < BT) {
        int ga = aBase + tid, gb = bBase + tid;
        aSq[tid] = g_sq[ga]; aP[tid] = g_pcl[ga]; aIW[tid] = g_invwnCls[ga];
        aCl[tid] = g_cls[ga];
        bSq[tid] = g_sq[gb]; bP[tid] = g_pcl[gb]; bIW[tid] = g_invwnCls[gb];
        bCl[tid] = g_cls[gb];
        rA0[tid] = 0.f; rA1[tid] = 0.f; rA2[tid] = 0.f;
        tB0[tid] = 0.f; tB1[tid] = 0.f; tB2[tid] = 0.f;
    }
    for (int i = tid; i < C * BT; i += 256) {
        int c = i >> 7, b = i & 127;
        projB[c][b] = g_proj[(size_t)(bBase + b) * C + c];
        projA[c][b] = g_proj[(size_t)(aBase + b) * C + c];
    }
    __syncthreads();
    if (tid < BT) {
        aIC[tid] = icT[aCl[tid]];
        bIC[tid] = icT[bCl[tid]];
    }

    float dacc[4][4][4];
    #pragma unroll
    for (int a = 0; a < 4; a++)
        #pragma unroll
        for (int b = 0; b < 4; b++)
            #pragma unroll
            for (int e = 0; e < 4; e++) dacc[a][b][e] = 0.f;

    // gmem-direct fragment pointers.
    // k-permutation: frag slot k^=t <-> phys 2t ; k^=t+4 <-> phys 2t+1
    // (identical for A and B, so the dot product is unchanged)
    const float* pA0 = pred + (size_t)(aBase + wm * 64 + g2) * D + 2 * tig;
    const float* pB0 = pred + (size_t)(bBase + wn * 32 + g2) * D + 2 * tig;

    #pragma unroll
    for (int ks = 0; ks < 16; ks++) {
        int kb = ks * 8;
        // load raw fp32 fragment pairs (LDG.64 each)
        float2 va[4][2], vb[4];
        #pragma unroll
        for (int fm = 0; fm < 4; fm++) {
            va[fm][0] = *(const float2*)(pA0 + fm * 16 * D + kb);
            va[fm][1] = *(const float2*)(pA0 + fm * 16 * D + 8 * D + kb);
        }
        #pragma unroll
        for (int fn = 0; fn < 4; fn++)
            vb[fn] = *(const float2*)(pB0 + fn * 8 * D + kb);

        // single-pass tf32 (rna): error ~2e-5 in M, well inside 1e-3 budget
        uint32_t Ah[4][4], Bh[4][2];
        #pragma unroll
        for (int fm = 0; fm < 4; fm++) {
            Ah[fm][0] = cvt_tf32(va[fm][0].x);    // row g2,   k^=t
            Ah[fm][1] = cvt_tf32(va[fm][1].x);    // row g2+8, k^=t
            Ah[fm][2] = cvt_tf32(va[fm][0].y);    // row g2,   k^=t+4
            Ah[fm][3] = cvt_tf32(va[fm][1].y);    // row g2+8, k^=t+4
        }
        #pragma unroll
        for (int fn = 0; fn < 4; fn++) {
            Bh[fn][0] = cvt_tf32(vb[fn].x);
            Bh[fn][1] = cvt_tf32(vb[fn].y);
        }
        #pragma unroll
        for (int fm = 0; fm < 4; fm++)
            #pragma unroll
            for (int fn = 0; fn < 4; fn++) mma_tf32(dacc[fm][fn], Ah[fm], Bh[fn]);
    }

    // -------- epilogue: per-pair loss from mma fragments --------
    float t0[8], t1[8], t2[8];
    #pragma unroll
    for (int j = 0; j < 8; j++) { t0[j] = 0.f; t1[j] = 0.f; t2[j] = 0.f; }

    #pragma unroll
    for (int fm = 0; fm < 4; fm++) {
        #pragma unroll
        for (int rr = 0; rr < 2; rr++) {
            int r = wm * 64 + fm * 16 + g2 + rr * 8;
            int   ca  = aCl[r];
            float pa  = aP[r], iw = aIW[r], ica = aIC[r], sqa = aSq[r];
            float s0 = 0.f, s1 = 0.f, s2 = 0.f;
            #pragma unroll
            for (int fn = 0; fn < 4; fn++) {
                #pragma unroll
                for (int hh = 0; hh < 2; hh++) {
                    int c = wn * 32 + fn * 8 + 2 * tig + hh;
                    float gv = dacc[fm][fn][rr * 2 + hh];
                    float d2 = fmaxf(sqa + bSq[c] - 2.0f * gv, 0.0f) + 1e-16f;
                    float invdn = fast_rsqrt(d2);
                    int cb = bCl[c];
                    if (cb != ca) {
                        float w = ica * bIC[c];
                        float MA = (pa - projB[ca][c]) * iw * invdn;
                        s0 += w; s1 = fmaf(w, MA, s1); s2 = fmaf(w * MA, MA, s2);
                        if (offd) {
                            float MB = (bP[c] - projA[cb][r]) * bIW[c] * invdn;
                            int j = fn * 2 + hh;
                            t0[j] += w; t1[j] = fmaf(w, MB, t1[j]); t2[j] = fmaf(w * MB, MB, t2[j]);
                        }
                    }
                }
            }
            atomicAdd(&rA0[r], s0); atomicAdd(&rA1[r], s1); atomicAdd(&rA2[r], s2);
        }
    }
    if (offd) {
        #pragma unroll
        for (int j = 0; j < 8; j++) {
            int c = wn * 32 + (j >> 1) * 8 + 2 * tig + (j & 1);
            atomicAdd(&tB0[c], t0[j]); atomicAdd(&tB1[c], t1[j]); atomicAdd(&tB2[c], t2[j]);
        }
    }
    __syncthreads();

    if (tid < BT) {
        int ca = aCl[tid];
        atomicAdd(&sacc[ca * 3 + 0], (double)rA0[tid]);
        atomicAdd(&sacc[ca * 3 + 1], (double)rA1[tid]);
        atomicAdd(&sacc[ca * 3 + 2], (double)rA2[tid]);
    } else if (offd) {
        int c = tid - BT;
        int cb = bCl[c];
        atomicAdd(&sacc[cb * 3 + 0], (double)tB0[c]);
        atomicAdd(&sacc[cb * 3 + 1], (double)tB1[c]);
        atomicAdd(&sacc[cb * 3 + 2], (double)tB2[c]);
    }
    __syncthreads();
    if (tid < 30) atomicAdd(&g_Sacc[tid], sacc[tid]);

    // -------- fused finalize --------
    __threadfence();
    __syncthreads();
    if (tid == 0) {
        unsigned int old = atomicAdd(&g_done, 1u);
        if (old == gridDim.x - 1) {
            __threadfence();
            int e = 0;
            for (int c = 0; c < C; c++) e += (g_counts[c] > 0);
            double ed  = (double)e;
            double inv = 1.0 / (ed - 1.0);
            double l1 = 0.0, l2 = 0.0;
            for (int c = 0; c < C; c++) {
                if (g_counts[c] > 0) {
                    double S0 = g_Sacc[c * 3 + 0];
                    double S1 = g_Sacc[c * 3 + 1];
                    double S2 = g_Sacc[c * 3 + 2];
                    l1 += (S0 - 2.0 * S1 + S2) * inv;
                    double mm = S1 * inv;
                    double mv = (S2 - 2.0 * mm * S1 + mm * mm * S0) * inv;
                    l2 += fabs(mv / mm);
                }
            }
            out[0] = (float)(l1 / ed);
            out[1] = (float)(l2 / ed);
            for (int i = 0; i < 32; i++) g_Sacc[i] = 0.0;
            for (int c = 0; c < C; c++)  g_counts[c] = 0;
            g_done = 0;
        }
    }
}

// ---------------- launch ----------------
extern "C" void kernel_launch(void* const* d_in, const int* in_sizes, int n_in,
                              void* d_out, int out_size)
{
    const float* pred   = (const float*)d_in[0];
    const int*   target = (const int*)d_in[1];   // JAX x64-disabled: int64 -> int32
    const float* W      = (const float*)d_in[2];
    int N = in_sizes[0] / D;                     // 4096
    int nb = N / BT;                             // 32
    int nblk = nb * (nb + 1) / 2;                // 528

    prep<<<(N + 127) / 128, 128>>>(pred, target, W, N);
    pairKernel<<<nblk, 256>>>(pred, (float*)d_out, nb);
}

// round 9
// speedup vs baseline: 1.6835x; 1.0021x over previous
#include <cuda_runtime.h>
#include <math.h>
#include <stdint.h>

#define D 128
#define C 10
#define NMAX 4096
#define BT 128
#define DYN_SMEM 65536   // 2 stages x (A 16KB + B 16KB)

// -------- device scratch (zero-init; finalize self-resets) --------
__device__ double g_Sacc[32];
__device__ int    g_counts[C];
__device__ float  g_sq[NMAX];
__device__ float  g_proj[NMAX * C];
__device__ int    g_cls[NMAX];
__device__ float  g_pcl[NMAX];
__device__ float  g_invwnCls[NMAX];
__device__ unsigned int g_done = 0;

__device__ __forceinline__ int clampC(int v) { return v < 0 ? 0 : (v >= C ? C - 1 : v); }

// rsqrt without MUFU: magic seed + 2 Newton steps (rel err ~4e-6)
__device__ __forceinline__ float fast_rsqrt(float x) {
    float y = __int_as_float(0x5f3759dfu - (__float_as_int(x) >> 1));
    float xh = -0.5f * x;
    y = y * fmaf(xh, y * y, 1.5f);
    y = y * fmaf(xh, y * y, 1.5f);
    return y;
}
__device__ __forceinline__ void mma_tf32(float* d, const uint32_t* a,
                                         uint32_t b0, uint32_t b1) {
    asm volatile(
        "mma.sync.aligned.m16n8k8.row.col.f32.tf32.tf32.f32 "
        "{%0,%1,%2,%3}, {%4,%5,%6,%7}, {%8,%9}, {%0,%1,%2,%3};"
        : "+f"(d[0]), "+f"(d[1]), "+f"(d[2]), "+f"(d[3])
        : "r"(a[0]), "r"(a[1]), "r"(a[2]), "r"(a[3]), "r"(b0), "r"(b1));
}
__device__ __forceinline__ uint32_t cvt_tf32(float v) {
    uint32_t u; asm("cvt.rna.tf32.f32 %0, %1;" : "=r"(u) : "f"(v)); return u;
}

// ---------------- prep: counts + per-row sq, proj[10], derived scalars -------
__global__ void prep(const float* __restrict__ pred,
                     const int* __restrict__ target,
                     const float* __restrict__ W, int N)
{
    __shared__ float Wsh[C][D];
    __shared__ float wnInv[C];
    __shared__ int   cnt[C];
    int tid = threadIdx.x;
    if (tid < C) cnt[tid] = 0;
    for (int i = tid; i < C * D; i += blockDim.x) Wsh[i / D][i % D] = W[i];
    __syncthreads();
    if (tid < C) {
        float s = 0.f;
        #pragma unroll 16
        for (int k = 0; k < D; k++) { float w = Wsh[tid][k]; s = fmaf(w, w, s); }
        wnInv[tid] = 1.0f / fmaxf(sqrtf(s), 1e-8f);
    }
    __syncthreads();

    int r = blockIdx.x * blockDim.x + tid;
    if (r < N) {
        int cl = clampC(target[r]);
        atomicAdd(&cnt[cl], 1);

        const float4* p4 = (const float4*)(pred + (size_t)r * D);
        float sq = 0.f;
        float proj[C];
        #pragma unroll
        for (int c = 0; c < C; c++) proj[c] = 0.f;
        #pragma unroll 4
        for (int q = 0; q < D / 4; q++) {
            float4 v = p4[q];
            float vv[4] = {v.x, v.y, v.z, v.w};
            #pragma unroll
            for (int j = 0; j < 4; j++) {
                float p = vv[j];
                int k = q * 4 + j;
                sq = fmaf(p, p, sq);
                #pragma unroll
                for (int c = 0; c < C; c++) proj[c] = fmaf(p, Wsh[c][k], proj[c]);
            }
        }
        g_sq[r]  = sq;
        g_cls[r] = cl;
        #pragma unroll
        for (int c = 0; c < C; c++) g_proj[(size_t)r * C + c] = proj[c];
        g_pcl[r]      = proj[cl];
        g_invwnCls[r] = wnInv[cl];
    }
    __syncthreads();
    if (tid < C && cnt[tid] > 0) atomicAdd(&g_counts[tid], cnt[tid]);
}

// ---- main: smem-staged fragment-major HMMA tf32 + fused loss epilogue -------
__global__ __launch_bounds__(256, 2)
void pairKernel(const float* __restrict__ pred, float* __restrict__ out, int nb)
{
    extern __shared__ uint32_t dyn[];   // [stage][A 4096w | B 4096w]
    __shared__ float projA[C][132];
    __shared__ float projB[C][132];
    __shared__ float aSq[BT], aP[BT], aIW[BT], aIC[BT];
    __shared__ float bSq[BT], bP[BT], bIW[BT], bIC[BT];
    __shared__ int   aCl[BT], bCl[BT];
    __shared__ float rA0[BT], rA1[BT], rA2[BT];
    __shared__ float tB0[BT], tB1[BT], tB2[BT];
    __shared__ float icT[16];
    __shared__ double sacc[32];

    int tid  = threadIdx.x;
    int lane = tid & 31, wid = tid >> 5;
    int wm = wid >> 2, wn = wid & 3;      // warp grid 2(m) x 4(n)
    int g2 = lane >> 2, tig = lane & 3;

    int idx = blockIdx.x;
    int bi = (int)(((float)(2 * nb + 1)
             - sqrtf((float)((2 * nb + 1) * (2 * nb + 1) - 8 * idx))) * 0.5f);
    while ((bi + 1) * nb - ((bi + 1) * bi) / 2 <= idx) bi++;
    while (bi * nb - (bi * (bi - 1)) / 2 > idx) bi--;
    int bj = bi + (idx - (bi * nb - (bi * (bi - 1)) / 2));
    int aBase = bi * BT, bBase = bj * BT;
    bool offd = (bi != bj);

    // ---- meta fill ----
    if (tid < 32) sacc[tid] = 0.0;
    if (tid < C)  icT[tid] = 1.0f / (float)max(g_counts[tid], 1);
    if (tid < BT) {
        int ga = aBase + tid, gb = bBase + tid;
        aSq[tid] = g_sq[ga]; aP[tid] = g_pcl[ga]; aIW[tid] = g_invwnCls[ga];
        aCl[tid] = g_cls[ga];
        bSq[tid] = g_sq[gb]; bP[tid] = g_pcl[gb]; bIW[tid] = g_invwnCls[gb];
        bCl[tid] = g_cls[gb];
        rA0[tid] = 0.f; rA1[tid] = 0.f; rA2[tid] = 0.f;
        tB0[tid] = 0.f; tB1[tid] = 0.f; tB2[tid] = 0.f;
    }
    for (int i = tid; i < C * BT; i += 256) {
        int c = i >> 7, b = i & 127;
        projB[c][b] = g_proj[(size_t)(bBase + b) * C + c];
        projA[c][b] = g_proj[(size_t)(aBase + b) * C + c];
    }
    __syncthreads();
    if (tid < BT) {
        aIC[tid] = icT[aCl[tid]];
        bIC[tid] = icT[bCl[tid]];
    }

    // ---- fill-index precompute (thread covers 4 float4 per tile per chunk) --
    // element (r, col): k8=col>>3, tl=col&3, th=(col>>2)&1, g2r=r&7
    // A word addr: ((r>>4)*4 + k8)*128 + g2r*16 + tl*4 + ((r>>3)&1) + 2*th
    // B word addr: (k8*8 + (r>>4))*128 + g2r*16 + tl*4 + ((r>>3)&1)*2 + th
    int gofs[4], aofs[4], bofs[4];
    #pragma unroll
    for (int i = 0; i < 4; i++) {
        int ix = i * 256 + tid;
        int r = ix >> 3, c = ix & 7;          // c = float4 column (0..7)
        gofs[i] = r * D + c * 4;
        aofs[i] = ((r >> 4) * 4 + (c >> 1)) * 128 + (r & 7) * 16
                + ((r >> 3) & 1) + ((c & 1) << 1);
        bofs[i] = ((c >> 1) * 8 + (r >> 4)) * 128 + (r & 7) * 16
                + (((r >> 3) & 1) << 1) + (c & 1);
    }
    const float* gA = pred + (size_t)aBase * D;
    const float* gB = pred + (size_t)bBase * D;

    float dacc[4][4][4];
    #pragma unroll
    for (int a = 0; a < 4; a++)
        #pragma unroll
        for (int b = 0; b < 4; b++)
            #pragma unroll
            for (int e = 0; e < 4; e++) dacc[a][b][e] = 0.f;

    // prefetch chunk 0
    float4 fa[4], fb[4];
    #pragma unroll
    for (int i = 0; i < 4; i++) {
        fa[i] = *(const float4*)(gA + gofs[i]);
        fb[i] = *(const float4*)(gB + gofs[i]);
    }

    #pragma unroll
    for (int ch = 0; ch < 4; ch++) {
        uint32_t* dA = dyn + (ch & 1) * 8192;
        uint32_t* dB = dA + 4096;
        // STS (convert to tf32 in-flight)
        #pragma unroll
        for (int i = 0; i < 4; i++) {
            dA[aofs[i] + 0]  = cvt_tf32(fa[i].x);
            dA[aofs[i] + 4]  = cvt_tf32(fa[i].y);
            dA[aofs[i] + 8]  = cvt_tf32(fa[i].z);
            dA[aofs[i] + 12] = cvt_tf32(fa[i].w);
            dB[bofs[i] + 0]  = cvt_tf32(fb[i].x);
            dB[bofs[i] + 4]  = cvt_tf32(fb[i].y);
            dB[bofs[i] + 8]  = cvt_tf32(fb[i].z);
            dB[bofs[i] + 12] = cvt_tf32(fb[i].w);
        }
        // prefetch next chunk (overlaps compute below)
        if (ch < 3) {
            int kb = (ch + 1) * 32;
            #pragma unroll
            for (int i = 0; i < 4; i++) {
                fa[i] = *(const float4*)(gA + kb + gofs[i]);
                fb[i] = *(const float4*)(gB + kb + gofs[i]);
            }
        }
        __syncthreads();
        // compute: 4 k8-steps, 6 LDS.128 + 16 HMMA per warp-step
        #pragma unroll
        for (int k8 = 0; k8 < 4; k8++) {
            uint4 bq0 = *(const uint4*)(dB + ((k8 * 8 + wn * 2 + 0) * 32 + lane) * 4);
            uint4 bq1 = *(const uint4*)(dB + ((k8 * 8 + wn * 2 + 1) * 32 + lane) * 4);
            #pragma unroll
            for (int fm = 0; fm < 4; fm++) {
                uint4 aq = *(const uint4*)(dA + (((wm * 4 + fm) * 4 + k8) * 32 + lane) * 4);
                uint32_t A4[4] = {aq.x, aq.y, aq.z, aq.w};
                mma_tf32(dacc[fm][0], A4, bq0.x, bq0.y);
                mma_tf32(dacc[fm][1], A4, bq0.z, bq0.w);
                mma_tf32(dacc[fm][2], A4, bq1.x, bq1.y);
                mma_tf32(dacc[fm][3], A4, bq1.z, bq1.w);
            }
        }
    }

    // -------- epilogue: per-pair loss from mma fragments --------
    float t0[8], t1[8], t2[8];
    #pragma unroll
    for (int j = 0; j < 8; j++) { t0[j] = 0.f; t1[j] = 0.f; t2[j] = 0.f; }

    #pragma unroll
    for (int fm = 0; fm < 4; fm++) {
        #pragma unroll
        for (int rr = 0; rr < 2; rr++) {
            int r = wm * 64 + fm * 16 + g2 + rr * 8;
            int   ca  = aCl[r];
            float pa  = aP[r], iw = aIW[r], ica = aIC[r], sqa = aSq[r];
            float s0 = 0.f, s1 = 0.f, s2 = 0.f;
            #pragma unroll
            for (int fn = 0; fn < 4; fn++) {
                #pragma unroll
                for (int hh = 0; hh < 2; hh++) {
                    int c = wn * 32 + fn * 8 + 2 * tig + hh;
                    float gv = dacc[fm][fn][rr * 2 + hh];
                    float d2 = fmaxf(sqa + bSq[c] - 2.0f * gv, 0.0f) + 1e-16f;
                    float invdn = fast_rsqrt(d2);
                    int cb = bCl[c];
                    if (cb != ca) {
                        float w = ica * bIC[c];
                        float MA = (pa - projB[ca][c]) * iw * invdn;
                        s0 += w; s1 = fmaf(w, MA, s1); s2 = fmaf(w * MA, MA, s2);
                        if (offd) {
                            float MB = (bP[c] - projA[cb][r]) * bIW[c] * invdn;
                            int j = fn * 2 + hh;
                            t0[j] += w; t1[j] = fmaf(w, MB, t1[j]); t2[j] = fmaf(w * MB, MB, t2[j]);
                        }
                    }
                }
            }
            atomicAdd(&rA0[r], s0); atomicAdd(&rA1[r], s1); atomicAdd(&rA2[r], s2);
        }
    }
    if (offd) {
        #pragma unroll
        for (int j = 0; j < 8; j++) {
            int c = wn * 32 + (j >> 1) * 8 + 2 * tig + (j & 1);
            atomicAdd(&tB0[c], t0[j]); atomicAdd(&tB1[c], t1[j]); atomicAdd(&tB2[c], t2[j]);
        }
    }
    __syncthreads();

    if (tid < BT) {
        int ca = aCl[tid];
        atomicAdd(&sacc[ca * 3 + 0], (double)rA0[tid]);
        atomicAdd(&sacc[ca * 3 + 1], (double)rA1[tid]);
        atomicAdd(&sacc[ca * 3 + 2], (double)rA2[tid]);
    } else if (offd) {
        int c = tid - BT;
        int cb = bCl[c];
        atomicAdd(&sacc[cb * 3 + 0], (double)tB0[c]);
        atomicAdd(&sacc[cb * 3 + 1], (double)tB1[c]);
        atomicAdd(&sacc[cb * 3 + 2], (double)tB2[c]);
    }
    __syncthreads();
    if (tid < 30) atomicAdd(&g_Sacc[tid], sacc[tid]);

    // -------- fused finalize --------
    __threadfence();
    __syncthreads();
    if (tid == 0) {
        unsigned int old = atomicAdd(&g_done, 1u);
        if (old == gridDim.x - 1) {
            __threadfence();
            int e = 0;
            for (int c = 0; c < C; c++) e += (g_counts[c] > 0);
            double ed  = (double)e;
            double inv = 1.0 / (ed - 1.0);
            double l1 = 0.0, l2 = 0.0;
            for (int c = 0; c < C; c++) {
                if (g_counts[c] > 0) {
                    double S0 = g_Sacc[c * 3 + 0];
                    double S1 = g_Sacc[c * 3 + 1];
                    double S2 = g_Sacc[c * 3 + 2];
                    l1 += (S0 - 2.0 * S1 + S2) * inv;
                    double mm = S1 * inv;
                    double mv = (S2 - 2.0 * mm * S1 + mm * mm * S0) * inv;
                    l2 += fabs(mv / mm);
                }
            }
            out[0] = (float)(l1 / ed);
            out[1] = (float)(l2 / ed);
            for (int i = 0; i < 32; i++) g_Sacc[i] = 0.0;
            for (int c = 0; c < C; c++)  g_counts[c] = 0;
            g_done = 0;
        }
    }
}

// ---------------- launch ----------------
extern "C" void kernel_launch(void* const* d_in, const int* in_sizes, int n_in,
                              void* d_out, int out_size)
{
    const float* pred   = (const float*)d_in[0];
    const int*   target = (const int*)d_in[1];   // JAX x64-disabled: int64 -> int32
    const float* W      = (const float*)d_in[2];
    int N = in_sizes[0] / D;                     // 4096
    int nb = N / BT;                             // 32
    int nblk = nb * (nb + 1) / 2;                // 528

    cudaFuncSetAttribute(pairKernel, cudaFuncAttributeMaxDynamicSharedMemorySize, DYN_SMEM);

    prep<<<(N + 127) / 128, 128>>>(pred, target, W, N);
    pairKernel<<<nblk, 256, DYN_SMEM>>>(pred, (float*)d_out, nb);
}

// round 10
// speedup vs baseline: 1.8497x; 1.0987x over previous
#include <cuda_runtime.h>
#include <math.h>
#include <stdint.h>

#define D 128
#define C 10
#define NMAX 4096
#define BT 128
#define GS 132                         // padded fragment-group stride (words)
#define STAGE_W (32 * GS)              // words per matrix per stage (4224)
#define DYN_SMEM (2 * 2 * STAGE_W * 4) // 67584 B

// -------- device scratch (zero-init; finalize self-resets) --------
__device__ double g_Sacc[32];
__device__ int    g_counts[C];
__device__ float  g_sq[NMAX];
__device__ float  g_projT[C * NMAX];   // [class][row], coalesced loads
__device__ int    g_cls[NMAX];
__device__ float  g_pcl[NMAX];
__device__ float  g_invwnCls[NMAX];
__device__ unsigned int g_done = 0;

__device__ __forceinline__ int clampC(int v) { return v < 0 ? 0 : (v >= C ? C - 1 : v); }

// rsqrt without MUFU: magic seed + 2 Newton steps (rel err ~4e-6)
__device__ __forceinline__ float fast_rsqrt(float x) {
    float y = __int_as_float(0x5f3759dfu - (__float_as_int(x) >> 1));
    float xh = -0.5f * x;
    y = y * fmaf(xh, y * y, 1.5f);
    y = y * fmaf(xh, y * y, 1.5f);
    return y;
}
__device__ __forceinline__ void mma_tf32(float* d, const uint32_t* a,
                                         uint32_t b0, uint32_t b1) {
    asm volatile(
        "mma.sync.aligned.m16n8k8.row.col.f32.tf32.tf32.f32 "
        "{%0,%1,%2,%3}, {%4,%5,%6,%7}, {%8,%9}, {%0,%1,%2,%3};"
        : "+f"(d[0]), "+f"(d[1]), "+f"(d[2]), "+f"(d[3])
        : "r"(a[0]), "r"(a[1]), "r"(a[2]), "r"(a[3]), "r"(b0), "r"(b1));
}
__device__ __forceinline__ uint32_t cvt_tf32(float v) {
    uint32_t u; asm("cvt.rna.tf32.f32 %0, %1;" : "=r"(u) : "f"(v)); return u;
}

// ---------------- prep: counts + per-row sq, projT, derived scalars ----------
__global__ void prep(const float* __restrict__ pred,
                     const int* __restrict__ target,
                     const float* __restrict__ W, int N)
{
    __shared__ float Wsh[C][D];
    __shared__ float wnInv[C];
    __shared__ int   cnt[C];
    int tid = threadIdx.x;
    if (tid < C) cnt[tid] = 0;
    for (int i = tid; i < C * D; i += blockDim.x) Wsh[i / D][i % D] = W[i];
    __syncthreads();
    if (tid < C) {
        float s = 0.f;
        #pragma unroll 16
        for (int k = 0; k < D; k++) { float w = Wsh[tid][k]; s = fmaf(w, w, s); }
        wnInv[tid] = 1.0f / fmaxf(sqrtf(s), 1e-8f);
    }
    __syncthreads();

    int r = blockIdx.x * blockDim.x + tid;
    if (r < N) {
        int cl = clampC(target[r]);
        atomicAdd(&cnt[cl], 1);

        const float4* p4 = (const float4*)(pred + (size_t)r * D);
        float sq = 0.f;
        float proj[C];
        #pragma unroll
        for (int c = 0; c < C; c++) proj[c] = 0.f;
        #pragma unroll 4
        for (int q = 0; q < D / 4; q++) {
            float4 v = p4[q];
            float vv[4] = {v.x, v.y, v.z, v.w};
            #pragma unroll
            for (int j = 0; j < 4; j++) {
                float p = vv[j];
                int k = q * 4 + j;
                sq = fmaf(p, p, sq);
                #pragma unroll
                for (int c = 0; c < C; c++) proj[c] = fmaf(p, Wsh[c][k], proj[c]);
            }
        }
        g_sq[r]  = sq;
        g_cls[r] = cl;
        #pragma unroll
        for (int c = 0; c < C; c++) g_projT[c * NMAX + r] = proj[c];
        g_pcl[r]      = proj[cl];
        g_invwnCls[r] = wnInv[cl];
    }
    __syncthreads();
    if (tid < C && cnt[tid] > 0) atomicAdd(&g_counts[tid], cnt[tid]);
}

// ---- main: smem-staged conflict-free HMMA tf32 + fused loss epilogue --------
__global__ __launch_bounds__(256, 2)
void pairKernel(const float* __restrict__ pred, float* __restrict__ out, int nb)
{
    extern __shared__ uint32_t dyn[];   // [stage][A STAGE_W | B STAGE_W]
    __shared__ float projA[C][132];
    __shared__ float projB[C][132];
    __shared__ float aSq[BT], aP[BT], aIW[BT], aIC[BT];
    __shared__ float bSq[BT], bP[BT], bIW[BT], bIC[BT];
    __shared__ int   aCl[BT], bCl[BT];
    __shared__ float rA0[BT], rA1[BT], rA2[BT];
    __shared__ float tB0[BT], tB1[BT], tB2[BT];
    __shared__ float icT[16];
    __shared__ double sacc[32];

    int tid  = threadIdx.x;
    int lane = tid & 31, wid = tid >> 5;
    int wm = wid >> 2, wn = wid & 3;      // warp grid 2(m) x 4(n)
    int g2 = lane >> 2, tig = lane & 3;

    int idx = blockIdx.x;
    int bi = (int)(((float)(2 * nb + 1)
             - sqrtf((float)((2 * nb + 1) * (2 * nb + 1) - 8 * idx))) * 0.5f);
    while ((bi + 1) * nb - ((bi + 1) * bi) / 2 <= idx) bi++;
    while (bi * nb - (bi * (bi - 1)) / 2 > idx) bi--;
    int bj = bi + (idx - (bi * nb - (bi * (bi - 1)) / 2));
    int aBase = bi * BT, bBase = bj * BT;
    bool offd = (bi != bj);

    // ---- meta fill (projA/projB now coalesced from g_projT) ----
    if (tid < 32) sacc[tid] = 0.0;
    if (tid < C)  icT[tid] = 1.0f / (float)max(g_counts[tid], 1);
    if (tid < BT) {
        int ga = aBase + tid, gb = bBase + tid;
        aSq[tid] = g_sq[ga]; aP[tid] = g_pcl[ga]; aIW[tid] = g_invwnCls[ga];
        aCl[tid] = g_cls[ga];
        bSq[tid] = g_sq[gb]; bP[tid] = g_pcl[gb]; bIW[tid] = g_invwnCls[gb];
        bCl[tid] = g_cls[gb];
        rA0[tid] = 0.f; rA1[tid] = 0.f; rA2[tid] = 0.f;
        tB0[tid] = 0.f; tB1[tid] = 0.f; tB2[tid] = 0.f;
    }
    for (int i = tid; i < C * BT; i += 256) {
        int c = i >> 7, b = i & 127;
        projB[c][b] = g_projT[c * NMAX + bBase + b];
        if (offd) projA[c][b] = g_projT[c * NMAX + aBase + b];
    }
    __syncthreads();
    if (tid < BT) {
        aIC[tid] = icT[aCl[tid]];
        bIC[tid] = icT[bCl[tid]];
    }

    // ---- fill-index precompute ----
    // A: group ga = m16*4 + k8, word = ga*GS + (r&7)*16 + ((r>>3)&1) + 2*(c&1), +4/word
    // B: group gb = n16*4 + k8, word = gb*GS + (r&7)*16 + 2*((r>>3)&1) + (c&1), +4/word
    // stride GS=132 => STS offsets across c are distinct mod 32 (conflict-free)
    int gofs[4], aofs[4], bofs[4];
    #pragma unroll
    for (int i = 0; i < 4; i++) {
        int ix = i * 256 + tid;
        int r = ix >> 3, c = ix & 7;          // c = float4 column (0..7)
        gofs[i] = r * D + c * 4;
        aofs[i] = ((r >> 4) * 4 + (c >> 1)) * GS + (r & 7) * 16
                + ((r >> 3) & 1) + ((c & 1) << 1);
        bofs[i] = ((r >> 4) * 4 + (c >> 1)) * GS + (r & 7) * 16
                + (((r >> 3) & 1) << 1) + (c & 1);
    }
    const float* gA = pred + (size_t)aBase * D;
    const float* gB = pred + (size_t)bBase * D;

    float dacc[4][4][4];
    #pragma unroll
    for (int a = 0; a < 4; a++)
        #pragma unroll
        for (int b = 0; b < 4; b++)
            #pragma unroll
            for (int e = 0; e < 4; e++) dacc[a][b][e] = 0.f;

    // prefetch chunk 0
    float4 fa[4], fb[4];
    #pragma unroll
    for (int i = 0; i < 4; i++) {
        fa[i] = *(const float4*)(gA + gofs[i]);
        fb[i] = *(const float4*)(gB + gofs[i]);
    }

    #pragma unroll
    for (int ch = 0; ch < 4; ch++) {
        uint32_t* dA = dyn + (ch & 1) * (2 * STAGE_W);
        uint32_t* dB = dA + STAGE_W;
        // STS (convert to tf32 in-flight); conflict-free via GS=132 padding
        #pragma unroll
        for (int i = 0; i < 4; i++) {
            dA[aofs[i] + 0]  = cvt_tf32(fa[i].x);
            dA[aofs[i] + 4]  = cvt_tf32(fa[i].y);
            dA[aofs[i] + 8]  = cvt_tf32(fa[i].z);
            dA[aofs[i] + 12] = cvt_tf32(fa[i].w);
            dB[bofs[i] + 0]  = cvt_tf32(fb[i].x);
            dB[bofs[i] + 4]  = cvt_tf32(fb[i].y);
            dB[bofs[i] + 8]  = cvt_tf32(fb[i].z);
            dB[bofs[i] + 12] = cvt_tf32(fb[i].w);
        }
        // prefetch next chunk (overlaps compute below)
        if (ch < 3) {
            int kb = (ch + 1) * 32;
            #pragma unroll
            for (int i = 0; i < 4; i++) {
                fa[i] = *(const float4*)(gA + kb + gofs[i]);
                fb[i] = *(const float4*)(gB + kb + gofs[i]);
            }
        }
        __syncthreads();
        // compute: 4 k8-steps, 6 LDS.128 + 16 HMMA per warp-step
        #pragma unroll
        for (int k8 = 0; k8 < 4; k8++) {
            uint4 bq0 = *(const uint4*)(dB + ((wn * 2 + 0) * 4 + k8) * GS + lane * 4);
            uint4 bq1 = *(const uint4*)(dB + ((wn * 2 + 1) * 4 + k8) * GS + lane * 4);
            #pragma unroll
            for (int fm = 0; fm < 4; fm++) {
                uint4 aq = *(const uint4*)(dA + ((wm * 4 + fm) * 4 + k8) * GS + lane * 4);
                uint32_t A4[4] = {aq.x, aq.y, aq.z, aq.w};
                mma_tf32(dacc[fm][0], A4, bq0.x, bq0.y);
                mma_tf32(dacc[fm][1], A4, bq0.z, bq0.w);
                mma_tf32(dacc[fm][2], A4, bq1.x, bq1.y);
                mma_tf32(dacc[fm][3], A4, bq1.z, bq1.w);
            }
        }
    }

    // -------- epilogue: per-pair loss from mma fragments --------
    // hoist c-side values once per thread (reused across all 8 rows)
    int   cV[8], cCl[8];
    float cSq[8], cIC[8];
    #pragma unroll
    for (int j = 0; j < 8; j++) {
        int c = wn * 32 + (j >> 1) * 8 + 2 * tig + (j & 1);
        cV[j] = c; cSq[j] = bSq[c]; cIC[j] = bIC[c]; cCl[j] = bCl[c];
    }
    float cP[8], cIW[8];
    if (offd) {
        #pragma unroll
        for (int j = 0; j < 8; j++) { cP[j] = bP[cV[j]]; cIW[j] = bIW[cV[j]]; }
    }

    float t0[8], t1[8], t2[8];
    #pragma unroll
    for (int j = 0; j < 8; j++) { t0[j] = 0.f; t1[j] = 0.f; t2[j] = 0.f; }

    #pragma unroll
    for (int fm = 0; fm < 4; fm++) {
        #pragma unroll
        for (int rr = 0; rr < 2; rr++) {
            int r = wm * 64 + fm * 16 + g2 + rr * 8;
            int   ca  = aCl[r];
            float pa  = aP[r], iw = aIW[r], ica = aIC[r], sqa = aSq[r];
            const float* pjr = projB[ca];
            float s0 = 0.f, s1 = 0.f, s2 = 0.f;
            #pragma unroll
            for (int j = 0; j < 8; j++) {
                float gv = dacc[fm][j >> 1][rr * 2 + (j & 1)];
                float d2 = fmaxf(sqa + cSq[j] - 2.0f * gv, 0.0f) + 1e-16f;
                float invdn = fast_rsqrt(d2);
                int cb = cCl[j];
                if (cb != ca) {
                    float w = ica * cIC[j];
                    float MA = (pa - pjr[cV[j]]) * iw * invdn;
                    s0 += w; s1 = fmaf(w, MA, s1); s2 = fmaf(w * MA, MA, s2);
                    if (offd) {
                        float MB = (cP[j] - projA[cb][r]) * cIW[j] * invdn;
                        t0[j] += w; t1[j] = fmaf(w, MB, t1[j]); t2[j] = fmaf(w * MB, MB, t2[j]);
                    }
                }
            }
            atomicAdd(&rA0[r], s0); atomicAdd(&rA1[r], s1); atomicAdd(&rA2[r], s2);
        }
    }
    if (offd) {
        #pragma unroll
        for (int j = 0; j < 8; j++) {
            atomicAdd(&tB0[cV[j]], t0[j]);
            atomicAdd(&tB1[cV[j]], t1[j]);
            atomicAdd(&tB2[cV[j]], t2[j]);
        }
    }
    __syncthreads();

    if (tid < BT) {
        int ca = aCl[tid];
        atomicAdd(&sacc[ca * 3 + 0], (double)rA0[tid]);
        atomicAdd(&sacc[ca * 3 + 1], (double)rA1[tid]);
        atomicAdd(&sacc[ca * 3 + 2], (double)rA2[tid]);
    } else if (offd) {
        int c = tid - BT;
        int cb = bCl[c];
        atomicAdd(&sacc[cb * 3 + 0], (double)tB0[c]);
        atomicAdd(&sacc[cb * 3 + 1], (double)tB1[c]);
        atomicAdd(&sacc[cb * 3 + 2], (double)tB2[c]);
    }
    __syncthreads();
    if (tid < 30) atomicAdd(&g_Sacc[tid], sacc[tid]);

    // -------- fused finalize --------
    __threadfence();
    __syncthreads();
    if (tid == 0) {
        unsigned int old = atomicAdd(&g_done, 1u);
        if (old == gridDim.x - 1) {
            __threadfence();
            int e = 0;
            for (int c = 0; c < C; c++) e += (g_counts[c] > 0);
            double ed  = (double)e;
            double inv = 1.0 / (ed - 1.0);
            double l1 = 0.0, l2 = 0.0;
            for (int c = 0; c < C; c++) {
                if (g_counts[c] > 0) {
                    double S0 = g_Sacc[c * 3 + 0];
                    double S1 = g_Sacc[c * 3 + 1];
                    double S2 = g_Sacc[c * 3 + 2];
                    l1 += (S0 - 2.0 * S1 + S2) * inv;
                    double mm = S1 * inv;
                    double mv = (S2 - 2.0 * mm * S1 + mm * mm * S0) * inv;
                    l2 += fabs(mv / mm);
                }
            }
            out[0] = (float)(l1 / ed);
            out[1] = (float)(l2 / ed);
            for (int i = 0; i < 32; i++) g_Sacc[i] = 0.0;
            for (int c = 0; c < C; c++)  g_counts[c] = 0;
            g_done = 0;
        }
    }
}

// ---------------- launch ----------------
extern "C" void kernel_launch(void* const* d_in, const int* in_sizes, int n_in,
                              void* d_out, int out_size)
{
    const float* pred   = (const float*)d_in[0];
    const int*   target = (const int*)d_in[1];   // JAX x64-disabled: int64 -> int32
    const float* W      = (const float*)d_in[2];
    int N = in_sizes[0] / D;                     // 4096
    int nb = N / BT;                             // 32
    int nblk = nb * (nb + 1) / 2;                // 528

    cudaFuncSetAttribute(pairKernel, cudaFuncAttributeMaxDynamicSharedMemorySize, DYN_SMEM);

    prep<<<(N + 127) / 128, 128>>>(pred, target, W, N);
    pairKernel<<<nblk, 256, DYN_SMEM>>>(pred, (float*)d_out, nb);
}